// round 13
// baseline (speedup 1.0000x reference)
#include <cuda_runtime.h>
#include <cstdint>

#define BB 16
#define NN 3000
#define MM 300
#define KK 4
#define LL 80
#define PCAP 128
#define GCAP 32
#define TPB 128
#define THRESH 0.6f
#define SCANB 104   // ceil(13200/128) scan blocks; always wave-1 resident

__device__ __forceinline__ float neg_inf() { return __int_as_float(0xff800000); }

// ---------------- global scratch (zero-init at load; kernel restores) ------
__device__ int g_pcnt[BB * LL];
__device__ int g_gcnt[BB * LL];
__device__ int g_pidx[BB * LL * PCAP];
__device__ int g_gidx[BB * LL * GCAP];
__device__ unsigned g_done;     // scan-completion counter (target SCANB)
__device__ unsigned g_depart;   // all-blocks depart counter (target grid)

// ---------------- exact-order IoU helpers (no FMA contraction) -------------
struct BoxA { float x0, y0, x1, y1, area; };

__device__ __forceinline__ BoxA cvt_box(float cx, float cy, float w, float h) {
    BoxA r;
    float hw = __fmul_rn(0.5f, w);
    float hh = __fmul_rn(0.5f, h);
    r.x0 = __fsub_rn(cx, hw);
    r.y0 = __fsub_rn(cy, hh);
    r.x1 = __fadd_rn(cx, hw);
    r.y1 = __fadd_rn(cy, hh);
    r.area = __fmul_rn(__fsub_rn(r.x1, r.x0), __fsub_rn(r.y1, r.y0));
    return r;
}

// a = gt box, b = proposal box (union = area_a + area_b - inter, in that order)
__device__ __forceinline__ float iou_ab(const BoxA& a, const BoxA& b) {
    float ltx = fmaxf(a.x0, b.x0);
    float lty = fmaxf(a.y0, b.y0);
    float rbx = fminf(a.x1, b.x1);
    float rby = fminf(a.y1, b.y1);
    float wx = fmaxf(__fsub_rn(rbx, ltx), 0.0f);
    float wy = fmaxf(__fsub_rn(rby, lty), 0.0f);
    float inter = __fmul_rn(wx, wy);
    float uni = __fsub_rn(__fadd_rn(a.area, b.area), inter);
    return __fdiv_rn(inter, fmaxf(uni, 1e-9f));
}

// total order: (value desc, index asc) — order-independent, tie-safe
__device__ __forceinline__ bool cmpvi(float v, int i, float w, int j) {
    return (v > w) || (v == w && i < j);
}

// ---------------- fused kernel ----------------------------------------------
__global__ void __launch_bounds__(TPB, 9)
kAll(const float* __restrict__ props,     // (B,N,4) cxcywh
     const int4*  __restrict__ pinds4,    // (B,N) as int4
     const int4*  __restrict__ gtl4,      // (B,M) as int4
     const float* __restrict__ gtb,       // (B,M,4) cxcywh
     float* __restrict__ out) {
    __shared__ float spx0[PCAP], spy0[PCAP], spx1[PCAP], spy1[PCAP], spar[PCAP];
    __shared__ int   spn[PCAP];
    __shared__ float sgx0[GCAP], sgy0[GCAP], sgx1[GCAP], sgy1[GCAP], sgar[GCAP], sgmx[GCAP];
    __shared__ int   sgm[GCAP];
    __shared__ int   scnt[GCAP];
    __shared__ float stv[GCAP * KK];
    __shared__ int   sti[GCAP * KK];
    __shared__ float siou[GCAP * PCAP];   // IoU matrix: computed once in phase A
    __shared__ int   s_pc, s_gc;

    const int bk = blockIdx.x;           // = b * LL + lab
    const int b  = bk / LL;
    const int t  = threadIdx.x;

    // ================= scan phase (blocks 0..SCANB-1 only) =================
    if (bk < SCANB) {
        int i = bk * TPB + t;
        if (i < BB * NN / 4) {
            int bb = i / (NN / 4);
            int n0 = (i % (NN / 4)) * 4;
            int4 v = pinds4[i];
            int labs[4] = {v.x, v.y, v.z, v.w};
#pragma unroll
            for (int q = 0; q < 4; q++) {
                int lab = labs[q];
                if ((unsigned)lab < LL) {
                    int dk = bb * LL + lab;
                    int slot = atomicAdd(&g_pcnt[dk], 1);
                    if (slot < PCAP) g_pidx[dk * PCAP + slot] = n0 + q;
                }
            }
        } else if (i < BB * NN / 4 + BB * MM / 4) {
            int j = i - BB * NN / 4;
            int bb = j / (MM / 4);
            int m0 = (j % (MM / 4)) * 4;
            int4 v = gtl4[j];
            int labs[4] = {v.x, v.y, v.z, v.w};
#pragma unroll
            for (int q = 0; q < 4; q++) {
                int lab = labs[q];
                if ((unsigned)lab < LL) {
                    int dk = bb * LL + lab;
                    int slot = atomicAdd(&g_gcnt[dk], 1);
                    if (slot < GCAP) g_gidx[dk * GCAP + slot] = m0 + q;
                }
            }
        }
        __threadfence();                 // publish scatter before arrival
    }
    __syncthreads();                     // whole block's scan complete

    // ============ deadlock-proof barrier: wait for 104 scan blocks =========
    if (t == 0) {
        if (bk < SCANB) atomicAdd(&g_done, 1u);
        while (*(volatile unsigned*)&g_done < SCANB) __nanosleep(64);
        __threadfence();                 // acquire: order bucket reads after flag
    }
    __syncthreads();

    // ================= bucket phase (identical to R11 body) =================
    // Slots >= count hold stale-but-valid indices; gathered but never consumed.
    int myn = g_pidx[bk * PCAP + t];
    if (t == 0) {
        s_pc = g_pcnt[bk];
        s_gc = g_gcnt[bk];
        g_pcnt[bk] = 0;                  // restore zero-invariant for graph replay
        g_gcnt[bk] = 0;
    }
    if (t < GCAP) scnt[t] = 0;

    {   // gather + convert proposal slot t
        float4 p4 = reinterpret_cast<const float4*>(props)[(size_t)b * NN + myn];
        BoxA p = cvt_box(p4.x, p4.y, p4.z, p4.w);
        spx0[t] = p.x0; spy0[t] = p.y0; spx1[t] = p.x1; spy1[t] = p.y1;
        spar[t] = p.area; spn[t] = myn;
    }
    if (t < GCAP) {                      // gather + convert GT slot t
        int mym = g_gidx[bk * GCAP + t];
        float4 g4 = reinterpret_cast<const float4*>(gtb)[(size_t)b * MM + mym];
        BoxA g = cvt_box(g4.x, g4.y, g4.z, g4.w);
        sgx0[t] = g.x0; sgy0[t] = g.y0; sgx1[t] = g.x1; sgy1[t] = g.y1;
        sgar[t] = g.area; sgm[t] = mym;
    }
    __syncthreads();

    const int gc = min(s_gc, GCAP);
    const int pc = min(s_pc, PCAP);

    if (gc != 0) {
        // ---- phase A: warp per GT -> IoU row (stored) + redux top-4 ----
        {
            const int warp = t >> 5, lane = t & 31;
            for (int j = warp; j < gc; j += TPB / 32) {
                BoxA g;
                g.x0 = sgx0[j]; g.y0 = sgy0[j]; g.x1 = sgx1[j]; g.y1 = sgy1[j]; g.area = sgar[j];

                float av0 = neg_inf(), av1 = neg_inf(), av2 = neg_inf(), av3 = neg_inf();
                int   an0 = 0x7fffffff, an1 = 0x7fffffff, an2 = 0x7fffffff, an3 = 0x7fffffff;
                for (int i = lane; i < pc; i += 32) {
                    BoxA p;
                    p.x0 = spx0[i]; p.y0 = spy0[i]; p.x1 = spx1[i]; p.y1 = spy1[i]; p.area = spar[i];
                    int n = spn[i];
                    float v = iou_ab(g, p);
                    siou[j * PCAP + i] = v;              // matrix row (conflict-free)
                    if (cmpvi(v, n, av3, an3)) {
                        if (cmpvi(v, n, av0, an0)) {
                            av3 = av2; an3 = an2; av2 = av1; an2 = an1; av1 = av0; an1 = an0;
                            av0 = v; an0 = n;
                        } else if (cmpvi(v, n, av1, an1)) {
                            av3 = av2; an3 = an2; av2 = av1; an2 = an1;
                            av1 = v; an1 = n;
                        } else if (cmpvi(v, n, av2, an2)) {
                            av3 = av2; an3 = an2;
                            av2 = v; an2 = n;
                        } else {
                            av3 = v; an3 = n;
                        }
                    }
                }

                // 4 extraction rounds via redux.sync (key: IoU>=0 -> bits|msb; sentinel 0)
#pragma unroll
                for (int r = 0; r < 4; r++) {
                    unsigned key = (av0 >= 0.0f) ? (__float_as_uint(av0) | 0x80000000u) : 0u;
                    unsigned kmax = __reduce_max_sync(0xffffffffu, key);
                    unsigned nmin = __reduce_min_sync(0xffffffffu,
                                        (key == kmax) ? (unsigned)an0 : 0xffffffffu);
                    float wv; int wn;
                    if (kmax != 0u) { wv = __uint_as_float(kmax & 0x7fffffffu); wn = (int)nmin; }
                    else            { wv = -1.0f; wn = 0; }
                    if (lane == r) { stv[j * KK + r] = wv; sti[j * KK + r] = wn; }
                    if (r == 0 && lane == 0) sgmx[j] = wv;   // row max (exact bits)
                    if (key == kmax && (unsigned)an0 == nmin) {
                        av0 = av1; an0 = an1; av1 = av2; an1 = an2;
                        av2 = av3; an2 = an3; av3 = neg_inf(); an3 = 0x7fffffff;
                    }
                }
            }
        }
        __syncthreads();

        // ---- phase B: thread i = proposal i; pure smem reads ----
        for (int i = t; i < pc; i += TPB) {
            float bestv = neg_inf();
            int bestm = 0x7fffffff, bestj = 0;
            bool lq = false;
            for (int j = 0; j < gc; j++) {
                float v = siou[j * PCAP + i];            // exact bits from phase A
                if (v == sgmx[j]) lq = true;
                int m = sgm[j];
                if (v > bestv || (v == bestv && m < bestm)) { bestv = v; bestm = m; bestj = j; }
            }
            if (bestv >= THRESH || lq)
                atomicAdd(&scnt[bestj], 1);
        }
        __syncthreads();

        // ---- phase C: thread j writes GT j's 16 output floats ----
        if (t < gc) {
            const int m = sgm[t];
            const int bm = b * MM + m;
            int take = scnt[t];
            take = take < KK ? take : KK;
            const int S = BB * MM * KK;
#pragma unroll
            for (int q = 0; q < KK; q++) {
                bool val = q < take;
                out[bm * KK + q]         = val ? (float)sti[t * KK + q] : -1.0f;
                out[S + bm * KK + q]     = val ? (float)m : -1.0f;
                out[2 * S + bm * KK + q] = val ? 1.0f : 0.0f;
                out[3 * S + bm * KK + q] = val ? stv[t * KK + q] : 0.0f;
            }
        }
    }

    // ============ depart + reset (every block, exactly once) ================
    __syncthreads();
    if (t == 0) {
        unsigned d = atomicAdd(&g_depart, 1u);
        if (d == (unsigned)gridDim.x - 1u) {   // last block out resets counters
            g_depart = 0;
            g_done = 0;
        }
    }
}

// ---------------- launch ----------------------------------------------------
extern "C" void kernel_launch(void* const* d_in, const int* in_sizes, int n_in,
                              void* d_out, int out_size) {
    // metadata order: pred_logits_match, pred_boxes, init_reference,
    //                 prompt_inds, gt_labels, gt_boxes, max_k
    const float* props = (const float*)d_in[2];   // init_reference (B,N,4)
    const int*   pinds = (const int*)d_in[3];     // prompt_inds    (B,N)
    const int*   gtl   = (const int*)d_in[4];     // gt_labels      (B,M)
    const float* gtb   = (const float*)d_in[5];   // gt_boxes       (B,M,4)

    kAll<<<BB * LL, TPB>>>(props, (const int4*)pinds, (const int4*)gtl,
                           gtb, (float*)d_out);
}

// round 14
// speedup vs baseline: 1.2899x; 1.2899x over previous
#include <cuda_runtime.h>
#include <cstdint>

#define BB 16
#define NN 3000
#define MM 300
#define KK 4
#define LL 80
#define PCAP 128
#define GCAP 32
#define TPB 128
#define THRESH 0.6f

__device__ __forceinline__ float neg_inf() { return __int_as_float(0xff800000); }

// ---------------- global bucket scratch (zero-init at load; kMain restores) -
__device__ int    g_pcnt[BB * LL];
__device__ int    g_gcnt[BB * LL];
__device__ float4 g_p1[BB * LL * PCAP];   // proposal (x0,y0,x1,y1) converted
__device__ float2 g_p2[BB * LL * PCAP];   // proposal (area, n_as_bits)
__device__ float4 g_g1[BB * LL * GCAP];   // gt (x0,y0,x1,y1) converted
__device__ float2 g_g2[BB * LL * GCAP];   // gt (area, m_as_bits)

// ---------------- exact-order IoU helpers (no FMA contraction) -------------
struct BoxA { float x0, y0, x1, y1, area; };

__device__ __forceinline__ BoxA cvt_box(float cx, float cy, float w, float h) {
    BoxA r;
    float hw = __fmul_rn(0.5f, w);
    float hh = __fmul_rn(0.5f, h);
    r.x0 = __fsub_rn(cx, hw);
    r.y0 = __fsub_rn(cy, hh);
    r.x1 = __fadd_rn(cx, hw);
    r.y1 = __fadd_rn(cy, hh);
    r.area = __fmul_rn(__fsub_rn(r.x1, r.x0), __fsub_rn(r.y1, r.y0));
    return r;
}

// a = gt box, b = proposal box (union = area_a + area_b - inter, in that order)
__device__ __forceinline__ float iou_ab(const BoxA& a, const BoxA& b) {
    float ltx = fmaxf(a.x0, b.x0);
    float lty = fmaxf(a.y0, b.y0);
    float rbx = fminf(a.x1, b.x1);
    float rby = fminf(a.y1, b.y1);
    float wx = fmaxf(__fsub_rn(rbx, ltx), 0.0f);
    float wy = fmaxf(__fsub_rn(rby, lty), 0.0f);
    float inter = __fmul_rn(wx, wy);
    float uni = __fsub_rn(__fadd_rn(a.area, b.area), inter);
    return __fdiv_rn(inter, fmaxf(uni, 1e-9f));
}

// total order: (value desc, index asc) — order-independent, tie-safe
__device__ __forceinline__ bool cmpvi(float v, int i, float w, int j) {
    return (v > w) || (v == w && i < j);
}

// ---------------- kernel S: vectorized scan -> converted record scatter -----
__global__ void __launch_bounds__(128) kS(const float* __restrict__ props,
                                          const int4* __restrict__ pinds4,
                                          const float* __restrict__ gtb,
                                          const int4* __restrict__ gtl4) {
    int i = blockIdx.x * 128 + threadIdx.x;
    if (i < BB * NN / 4) {
        int b = i / (NN / 4);
        int n0 = (i % (NN / 4)) * 4;
        int4 v = pinds4[i];
        int labs[4] = {v.x, v.y, v.z, v.w};
#pragma unroll
        for (int q = 0; q < 4; q++) {
            int lab = labs[q];
            if ((unsigned)lab < LL) {
                int bk = b * LL + lab;
                int slot = atomicAdd(&g_pcnt[bk], 1);
                if (slot < PCAP) {
                    int n = n0 + q;
                    float4 p4 = reinterpret_cast<const float4*>(props)[(size_t)b * NN + n];
                    BoxA p = cvt_box(p4.x, p4.y, p4.z, p4.w);
                    size_t idx = (size_t)bk * PCAP + slot;
                    g_p1[idx] = make_float4(p.x0, p.y0, p.x1, p.y1);
                    g_p2[idx] = make_float2(p.area, __int_as_float(n));
                }
            }
        }
    } else if (i < BB * NN / 4 + BB * MM / 4) {
        int j = i - BB * NN / 4;
        int b = j / (MM / 4);
        int m0 = (j % (MM / 4)) * 4;
        int4 v = gtl4[j];
        int labs[4] = {v.x, v.y, v.z, v.w};
#pragma unroll
        for (int q = 0; q < 4; q++) {
            int lab = labs[q];
            if ((unsigned)lab < LL) {
                int bk = b * LL + lab;
                int slot = atomicAdd(&g_gcnt[bk], 1);
                if (slot < GCAP) {
                    int m = m0 + q;
                    float4 g4 = reinterpret_cast<const float4*>(gtb)[(size_t)b * MM + m];
                    BoxA g = cvt_box(g4.x, g4.y, g4.z, g4.w);
                    size_t idx = (size_t)bk * GCAP + slot;
                    g_g1[idx] = make_float4(g.x0, g.y0, g.x1, g.y1);
                    g_g2[idx] = make_float2(g.area, __int_as_float(m));
                }
            }
        }
    }
}

// ---------------- kernel M: one block per (batch,label) bucket --------------
// minnctapersm=9 -> 9 blocks/SM -> 1332 slots >= 1280 blocks: ONE wave
__global__ void __launch_bounds__(TPB, 9)
kMain(float* __restrict__ out) {
    __shared__ float spx0[PCAP], spy0[PCAP], spx1[PCAP], spy1[PCAP], spar[PCAP];
    __shared__ int   spn[PCAP];
    __shared__ float sgx0[GCAP], sgy0[GCAP], sgx1[GCAP], sgy1[GCAP], sgar[GCAP], sgmx[GCAP];
    __shared__ int   sgm[GCAP];
    __shared__ int   scnt[GCAP];
    __shared__ float stv[GCAP * KK];
    __shared__ int   sti[GCAP * KK];
    __shared__ float siou[GCAP * PCAP];   // IoU matrix: computed once in phase A
    __shared__ int   s_pc, s_gc;

    const int bk = blockIdx.x;           // = b * LL + lab
    const int b  = bk / LL;
    const int t  = threadIdx.x;

    // ---- single-hop record loads (all independent; stale slots never consumed) ----
    float4 q1 = g_p1[(size_t)bk * PCAP + t];
    float2 q2 = g_p2[(size_t)bk * PCAP + t];
    if (t == 0) {
        s_pc = g_pcnt[bk];
        s_gc = g_gcnt[bk];
        g_pcnt[bk] = 0;                  // restore zero-invariant for graph replay
        g_gcnt[bk] = 0;
    }
    if (t < GCAP) scnt[t] = 0;

    spx0[t] = q1.x; spy0[t] = q1.y; spx1[t] = q1.z; spy1[t] = q1.w;
    spar[t] = q2.x; spn[t] = __float_as_int(q2.y);

    if (t < GCAP) {
        float4 r1 = g_g1[(size_t)bk * GCAP + t];
        float2 r2 = g_g2[(size_t)bk * GCAP + t];
        sgx0[t] = r1.x; sgy0[t] = r1.y; sgx1[t] = r1.z; sgy1[t] = r1.w;
        sgar[t] = r2.x; sgm[t] = __float_as_int(r2.y);
    }
    __syncthreads();

    const int gc = min(s_gc, GCAP);
    if (gc == 0) return;                 // no GT rows owned by this block
    const int pc = min(s_pc, PCAP);

    // ---- phase A: warp per GT -> IoU row (stored) + redux top-4 extraction ----
    {
        const int warp = t >> 5, lane = t & 31;
        for (int j = warp; j < gc; j += TPB / 32) {
            BoxA g;
            g.x0 = sgx0[j]; g.y0 = sgy0[j]; g.x1 = sgx1[j]; g.y1 = sgy1[j]; g.area = sgar[j];

            // per-lane sorted-4 candidates (<=4 items since pc<=128)
            float av0 = neg_inf(), av1 = neg_inf(), av2 = neg_inf(), av3 = neg_inf();
            int   an0 = 0x7fffffff, an1 = 0x7fffffff, an2 = 0x7fffffff, an3 = 0x7fffffff;
            for (int i = lane; i < pc; i += 32) {
                BoxA p;
                p.x0 = spx0[i]; p.y0 = spy0[i]; p.x1 = spx1[i]; p.y1 = spy1[i]; p.area = spar[i];
                int n = spn[i];
                float v = iou_ab(g, p);
                siou[j * PCAP + i] = v;              // matrix row (conflict-free)
                if (cmpvi(v, n, av3, an3)) {
                    if (cmpvi(v, n, av0, an0)) {
                        av3 = av2; an3 = an2; av2 = av1; an2 = an1; av1 = av0; an1 = an0;
                        av0 = v; an0 = n;
                    } else if (cmpvi(v, n, av1, an1)) {
                        av3 = av2; an3 = an2; av2 = av1; an2 = an1;
                        av1 = v; an1 = n;
                    } else if (cmpvi(v, n, av2, an2)) {
                        av3 = av2; an3 = an2;
                        av2 = v; an2 = n;
                    } else {
                        av3 = v; an3 = n;
                    }
                }
            }

            // 4 extraction rounds via redux.sync (key: IoU>=0 -> bits|msb; sentinel 0)
#pragma unroll
            for (int r = 0; r < 4; r++) {
                unsigned key = (av0 >= 0.0f) ? (__float_as_uint(av0) | 0x80000000u) : 0u;
                unsigned kmax = __reduce_max_sync(0xffffffffu, key);
                unsigned nmin = __reduce_min_sync(0xffffffffu,
                                    (key == kmax) ? (unsigned)an0 : 0xffffffffu);
                float wv; int wn;
                if (kmax != 0u) { wv = __uint_as_float(kmax & 0x7fffffffu); wn = (int)nmin; }
                else            { wv = -1.0f; wn = 0; }
                if (lane == r) { stv[j * KK + r] = wv; sti[j * KK + r] = wn; }
                if (r == 0 && lane == 0) sgmx[j] = wv;   // row max (exact bits)
                // winner advances its candidate shift-register
                if (key == kmax && (unsigned)an0 == nmin) {
                    av0 = av1; an0 = an1; av1 = av2; an1 = an2;
                    av2 = av3; an2 = an3; av3 = neg_inf(); an3 = 0x7fffffff;
                }
            }
        }
    }
    __syncthreads();

    // ---- phase B: thread i = proposal i; pure smem reads (no IoU recompute) ----
    for (int i = t; i < pc; i += TPB) {
        float bestv = neg_inf();
        int bestm = 0x7fffffff, bestj = 0;
        bool lq = false;
        for (int j = 0; j < gc; j++) {
            float v = siou[j * PCAP + i];            // exact bits from phase A
            if (v == sgmx[j]) lq = true;
            int m = sgm[j];
            if (v > bestv || (v == bestv && m < bestm)) { bestv = v; bestm = m; bestj = j; }
        }
        // matching IoU >= 0 beats all non-matching NEG entries -> bestm == ref best_gt
        if (bestv >= THRESH || lq)
            atomicAdd(&scnt[bestj], 1);
    }
    __syncthreads();

    // ---- phase C: thread j writes GT j's 16 output floats ----
    if (t < gc) {
        const int m = sgm[t];
        const int bm = b * MM + m;
        int take = scnt[t];
        take = take < KK ? take : KK;
        const int S = BB * MM * KK;
#pragma unroll
        for (int q = 0; q < KK; q++) {
            bool val = q < take;
            out[bm * KK + q]         = val ? (float)sti[t * KK + q] : -1.0f;
            out[S + bm * KK + q]     = val ? (float)m : -1.0f;
            out[2 * S + bm * KK + q] = val ? 1.0f : 0.0f;
            out[3 * S + bm * KK + q] = val ? stv[t * KK + q] : 0.0f;
        }
    }
}

// ---------------- launch ----------------------------------------------------
extern "C" void kernel_launch(void* const* d_in, const int* in_sizes, int n_in,
                              void* d_out, int out_size) {
    // metadata order: pred_logits_match, pred_boxes, init_reference,
    //                 prompt_inds, gt_labels, gt_boxes, max_k
    const float* props = (const float*)d_in[2];   // init_reference (B,N,4)
    const int*   pinds = (const int*)d_in[3];     // prompt_inds    (B,N)
    const int*   gtl   = (const int*)d_in[4];     // gt_labels      (B,M)
    const float* gtb   = (const float*)d_in[5];   // gt_boxes       (B,M,4)

    const int nscan = BB * NN / 4 + BB * MM / 4;  // 13200
    kS<<<(nscan + 127) / 128, 128>>>(props, (const int4*)pinds,
                                     gtb, (const int4*)gtl);
    kMain<<<BB * LL, TPB>>>((float*)d_out);
}